// round 7
// baseline (speedup 1.0000x reference)
#include <cuda_runtime.h>
#include <cstdint>

// ConLoss via mma.sync tf32 + class member lists.
//   k0: target dtype detect
//   k1: row normalize + tf32-round + K-pair-permute store
//   k2b: deterministic counting sort -> per-class member lists
//   k2: triangular 128x128 tf32 mma tiles (cp.async double-buffered) ->
//       exp tile to g_S + neg partials
//   k3: per-row positive gather via member list
//   k4: final reduction
// Deterministic: no fp atomics; fixed-order reductions; stable sort.

#define CN 4096
#define CD 512
#define BM 128
#define NT (CN / BM)                  // 32
#define NPAIRS (NT * (NT + 1) / 2)    // 528
#define KC 32
#define NCHUNK (CD / KC)              // 16
#define KSTRIDE 36                    // padded smem row stride (floats)
#define NCLS 128                      // >= NUM_CLASSES(100), padded
#define EXP2SCALE 14.4269504088896340736f   // (1/TAU)*log2(e)

// ---- scratch ----
__device__ float g_Fn[CN * CD];                  // tf32-rounded, K-pair-permuted
__device__ int   g_cls[CN];
__device__ float g_negpart[NT * CN];
__device__ float g_S[(size_t)NPAIRS * BM * BM];  // 34.6 MB exp(S/tau) tiles
__device__ float g_rowloss[CN];
__device__ int   g_rowP[CN];
__device__ int   g_is64;
__device__ int   g_mlist[CN];                    // members sorted by (class, j)
__device__ int   g_clsOff[NCLS];
__device__ int   g_clsCnt[NCLS];

__device__ __forceinline__ uint32_t smem_u32(const void* p) {
    uint32_t a;
    asm("{ .reg .u64 t; cvta.to.shared.u64 t, %1; cvt.u32.u64 %0, t; }" : "=r"(a) : "l"(p));
    return a;
}
__device__ __forceinline__ void cp16(uint32_t saddr, const void* g) {
    asm volatile("cp.async.cg.shared.global [%0], [%1], 16;" :: "r"(saddr), "l"(g) : "memory");
}
#define CP_COMMIT() asm volatile("cp.async.commit_group;" ::: "memory")
#define CP_WAIT(n)  asm volatile("cp.async.wait_group %0;" :: "n"(n) : "memory")

// ============ kernel 0: detect targets dtype (int32 vs int64) ============
__global__ void k0_detect(const int* __restrict__ t32) {
    __shared__ int bad;
    if (threadIdx.x == 0) bad = 0;
    __syncthreads();
    for (int idx = 1 + 2 * threadIdx.x; idx < CN; idx += 2 * blockDim.x)
        if (t32[idx] != 0) bad = 1;
    __syncthreads();
    if (threadIdx.x == 0) g_is64 = bad ? 0 : 1;
}

// ============ kernel 1: normalize + tf32 round + permute store ============
// Permutation within each 8-float K group: pos 2t <- k=t, pos 2t+1 <- k=t+4.
// Gram sums are K-order invariant; mma (k,k+4) pairs become LDS.64-adjacent.
__global__ void k1_normalize(const float* __restrict__ F,
                             const int* __restrict__ t32) {
    int row = blockIdx.x;
    int tid = threadIdx.x;  // 128
    const float4* fr = (const float4*)(F + (size_t)row * CD);
    float4 x = fr[tid];
    float ss = x.x * x.x + x.y * x.y + x.z * x.z + x.w * x.w;
    #pragma unroll
    for (int o = 16; o > 0; o >>= 1) ss += __shfl_xor_sync(0xffffffffu, ss, o);
    __shared__ float ws[4];
    __shared__ float s_inv;
    int wid = tid >> 5, lane = tid & 31;
    if (lane == 0) ws[wid] = ss;
    __syncthreads();
    if (tid == 0) {
        float t = ws[0] + ws[1] + ws[2] + ws[3];
        s_inv = (t > 0.0f) ? rsqrtf(t) : 0.0f;
        g_cls[row] = g_is64 ? t32[2 * row] : t32[row];
    }
    __syncthreads();
    float inv = s_inv;
    float v[4] = {x.x * inv, x.y * inv, x.z * inv, x.w * inv};
    uint32_t bits[4];
    #pragma unroll
    for (int q = 0; q < 4; q++)
        asm("cvt.rna.tf32.f32 %0, %1;" : "=r"(bits[q]) : "f"(v[q]));
    // thread covers k = 4*tid..4*tid+3, all in group g=tid>>1; within-group
    // k' = (tid&1)*4+q -> perm pos = 2q + (tid&1)
    float* dst = g_Fn + (size_t)row * CD + (tid >> 1) * 8 + (tid & 1);
    #pragma unroll
    for (int q = 0; q < 4; q++) dst[2 * q] = __uint_as_float(bits[q]);
}

// ============ kernel 2b: deterministic class member lists ============
__global__ __launch_bounds__(1024) void k2b_lists() {
    __shared__ int sCls[CN];            // 16 KB
    __shared__ int cnt[8][NCLS];        // chunk x class counts
    __shared__ int chOff[8][NCLS];
    __shared__ int clsOff[NCLS];
    int tid = threadIdx.x;
    for (int t = tid; t < CN; t += 1024) sCls[t] = g_cls[t];
    for (int t = tid; t < 8 * NCLS; t += 1024) ((int*)cnt)[t] = 0;
    __syncthreads();
    int ch = tid >> 7, sub = tid & 127;
    #pragma unroll
    for (int i = 0; i < 4; i++) {
        int j = ch * 512 + sub + i * 128;
        atomicAdd(&cnt[ch][sCls[j]], 1);     // integer counts: deterministic
    }
    __syncthreads();
    if (tid == 0) {
        int off = 0;
        for (int c = 0; c < NCLS; c++) {
            int tot = 0;
            #pragma unroll
            for (int h = 0; h < 8; h++) tot += cnt[h][c];
            clsOff[c] = off;
            g_clsOff[c] = off;
            g_clsCnt[c] = tot;
            off += tot;
        }
    }
    __syncthreads();
    if (tid < NCLS) {
        int run = clsOff[tid];
        #pragma unroll
        for (int h = 0; h < 8; h++) { chOff[h][tid] = run; run += cnt[h][tid]; }
    }
    __syncthreads();
    // stable placement: one thread per (chunk, class), scan chunk in j order
    if (tid < 8 * NCLS) {
        int c = tid & (NCLS - 1), h = tid >> 7;
        int pos = chOff[h][c];
        for (int j = h * 512; j < h * 512 + 512; j++)
            if (sCls[j] == c) g_mlist[pos++] = j;
    }
}

// ============ kernel 2: triangular Gram via mma.sync tf32 ============
// smem: stage[2]{ A[128*36] | B[128*36] } | clsI | clsJ | sMatR[2][128] | sMatC[4][128]
#define STAGE_F (2 * 128 * KSTRIDE)      // floats per stage (A+B) = 9216
#define SM_EXTRA_OFF (2 * STAGE_F)       // 18432
#define SM_FLOATS (SM_EXTRA_OFF + 128 + 128 + 256 + 512)
#define SMEMSZ (SM_FLOATS * 4)

__global__ __launch_bounds__(256, 2) void k2_gram_mma() {
    extern __shared__ float smem[];
    int* clsI = (int*)(smem + SM_EXTRA_OFF);
    int* clsJ = clsI + 128;
    float* sMatR = (float*)(clsJ + 128);   // [2][128]
    float* sMatC = sMatR + 256;            // [4][128]

    int tid = threadIdx.x, wid = tid >> 5, lane = tid & 31;
    int b = blockIdx.x;
    int jT = (int)((sqrtf(8.0f * b + 1.0f) - 1.0f) * 0.5f);
    while ((jT + 1) * (jT + 2) / 2 <= b) jT++;
    while (jT * (jT + 1) / 2 > b) jT--;
    int iT = b - jT * (jT + 1) / 2;
    int i0 = iT * BM, j0 = jT * BM;
    bool diag = (iT == jT);

    if (tid < 128) {
        clsI[tid] = g_cls[i0 + tid];
        clsJ[tid] = g_cls[j0 + tid];
    }

    // loader mapping: thread -> (matrix, row); 8 x cp.async(16B) per chunk
    int mat = tid >> 7, lrow = tid & 127;
    const float* gsrc = g_Fn + (size_t)((mat ? j0 : i0) + lrow) * CD;
    uint32_t sdst0 = smem_u32(smem) + (uint32_t)(mat * 128 * KSTRIDE + lrow * KSTRIDE) * 4u;

    // prefetch chunks 0 and 1
    #pragma unroll
    for (int s = 0; s < 2; s++) {
        const float* src = gsrc + s * KC;
        uint32_t dst = sdst0 + (uint32_t)(s * STAGE_F) * 4u;
        #pragma unroll
        for (int i = 0; i < 8; i++) cp16(dst + i * 16u, src + i * 4);
        CP_COMMIT();
    }

    int wm = wid & 3, wn = wid >> 2;        // 4 x 2 warp grid
    int mrow0 = wm * 32, ncol0 = wn * 64;   // warp tile 32x64

    float acc[2][8][4];
    #pragma unroll
    for (int mf = 0; mf < 2; mf++)
        #pragma unroll
        for (int nf = 0; nf < 8; nf++)
            #pragma unroll
            for (int q = 0; q < 4; q++) acc[mf][nf][q] = 0.0f;

    int ar = mrow0 + (lane >> 2);
    int bcol = (lane >> 2);
    int kbase = 2 * (lane & 3);

    for (int c = 0; c < NCHUNK; c++) {
        if (c + 2 < NCHUNK) { CP_WAIT(1); } else { CP_WAIT(0); }
        __syncthreads();
        const float* As = smem + (c & 1) * STAGE_F;
        const float* Bs = As + 128 * KSTRIDE;
        #pragma unroll
        for (int kk = 0; kk < KC; kk += 8) {
            int koff = kk + kbase;
            uint2 ua[2][2];
            #pragma unroll
            for (int mf = 0; mf < 2; mf++) {
                ua[mf][0] = *(const uint2*)(As + (ar + mf * 16) * KSTRIDE + koff);
                ua[mf][1] = *(const uint2*)(As + (ar + mf * 16 + 8) * KSTRIDE + koff);
            }
            #pragma unroll
            for (int nf = 0; nf < 8; nf++) {
                uint2 ub = *(const uint2*)(Bs + (ncol0 + nf * 8 + bcol) * KSTRIDE + koff);
                #pragma unroll
                for (int mf = 0; mf < 2; mf++) {
                    asm volatile(
                        "mma.sync.aligned.m16n8k8.row.col.f32.tf32.tf32.f32 "
                        "{%0,%1,%2,%3}, {%4,%5,%6,%7}, {%8,%9}, {%0,%1,%2,%3};"
                        : "+f"(acc[mf][nf][0]), "+f"(acc[mf][nf][1]),
                          "+f"(acc[mf][nf][2]), "+f"(acc[mf][nf][3])
                        : "r"(ua[mf][0].x), "r"(ua[mf][1].x),
                          "r"(ua[mf][0].y), "r"(ua[mf][1].y),
                          "r"(ub.x), "r"(ub.y));
                }
            }
        }
        __syncthreads();
        if (c + 2 < NCHUNK) {
            const float* src = gsrc + (c + 2) * KC;
            uint32_t dst = sdst0 + (uint32_t)((c & 1) * STAGE_F) * 4u;
            #pragma unroll
            for (int i = 0; i < 8; i++) cp16(dst + i * 16u, src + i * 4);
            CP_COMMIT();
        }
    }

    // ---- epilogue: exp, mask, deterministic row/col partials, g_S store ----
    size_t pairBase = (size_t)b * (BM * BM);
    float rowP[2][2] = {{0, 0}, {0, 0}};
    float colP[8][2];
    #pragma unroll
    for (int nf = 0; nf < 8; nf++) { colP[nf][0] = 0.0f; colP[nf][1] = 0.0f; }

    int rr = mrow0 + (lane >> 2);
    int cc0 = ncol0 + (lane & 3) * 2;
    #pragma unroll
    for (int mf = 0; mf < 2; mf++) {
        int r = rr + mf * 16;
        int ci0 = clsI[r], ci1 = clsI[r + 8];
        #pragma unroll
        for (int nf = 0; nf < 8; nf++) {
            int col = cc0 + nf * 8;
            int cj0 = clsJ[col], cj1 = clsJ[col + 1];
            float e00 = exp2f(acc[mf][nf][0] * EXP2SCALE);
            float e01 = exp2f(acc[mf][nf][1] * EXP2SCALE);
            float e10 = exp2f(acc[mf][nf][2] * EXP2SCALE);
            float e11 = exp2f(acc[mf][nf][3] * EXP2SCALE);
            *(float2*)(g_S + pairBase + (size_t)r * BM + col) = make_float2(e00, e01);
            *(float2*)(g_S + pairBase + (size_t)(r + 8) * BM + col) = make_float2(e10, e11);
            float m00 = (ci0 != cj0) ? e00 : 0.0f;
            float m01 = (ci0 != cj1) ? e01 : 0.0f;
            float m10 = (ci1 != cj0) ? e10 : 0.0f;
            float m11 = (ci1 != cj1) ? e11 : 0.0f;
            rowP[mf][0] += m00 + m01;
            rowP[mf][1] += m10 + m11;
            colP[nf][0] += m00 + m10;
            colP[nf][1] += m01 + m11;
        }
    }
    #pragma unroll
    for (int mf = 0; mf < 2; mf++)
        #pragma unroll
        for (int h = 0; h < 2; h++) {
            float v = rowP[mf][h];
            v += __shfl_xor_sync(0xffffffffu, v, 1);
            v += __shfl_xor_sync(0xffffffffu, v, 2);
            rowP[mf][h] = v;
        }
    if ((lane & 3) == 0) {
        #pragma unroll
        for (int mf = 0; mf < 2; mf++) {
            int r = rr + mf * 16;
            sMatR[wn * 128 + r] = rowP[mf][0];
            sMatR[wn * 128 + r + 8] = rowP[mf][1];
        }
    }
    #pragma unroll
    for (int nf = 0; nf < 8; nf++)
        #pragma unroll
        for (int h = 0; h < 2; h++) {
            float v = colP[nf][h];
            v += __shfl_xor_sync(0xffffffffu, v, 4);
            v += __shfl_xor_sync(0xffffffffu, v, 8);
            v += __shfl_xor_sync(0xffffffffu, v, 16);
            colP[nf][h] = v;
        }
    if (lane < 4) {
        #pragma unroll
        for (int nf = 0; nf < 8; nf++) {
            int col = ncol0 + nf * 8 + lane * 2;
            sMatC[wm * 128 + col] = colP[nf][0];
            sMatC[wm * 128 + col + 1] = colP[nf][1];
        }
    }
    __syncthreads();
    if (tid < 128) {
        g_negpart[(size_t)jT * CN + i0 + tid] = sMatR[tid] + sMatR[128 + tid];
        if (!diag)
            g_negpart[(size_t)iT * CN + j0 + tid] =
                sMatC[tid] + sMatC[128 + tid] + sMatC[256 + tid] + sMatC[384 + tid];
    }
}

// ============ kernel 3: per-row positive gather (member lists) ============
__global__ __launch_bounds__(256) void k3_rowloss() {
    int tid = threadIdx.x, wid = tid >> 5, lane = tid & 31;
    int row = blockIdx.x * 8 + wid;

    float v = g_negpart[(size_t)lane * CN + row];
    #pragma unroll
    for (int o = 16; o > 0; o >>= 1) v += __shfl_xor_sync(0xffffffffu, v, o);
    float neg = v;

    int ci = g_cls[row];
    int off = g_clsOff[ci], cnt = g_clsCnt[ci];
    int ti = row >> 7, ri = row & 127;
    float sum = 0.0f;
    for (int m = lane; m < cnt; m += 32) {
        int j = g_mlist[off + m];
        if (j != row) {
            int tj = j >> 7, rj = j & 127;
            size_t idx = (ti <= tj)
                ? ((size_t)(tj * (tj + 1) / 2 + ti)) * 16384 + (size_t)ri * 128 + rj
                : ((size_t)(ti * (ti + 1) / 2 + tj)) * 16384 + (size_t)rj * 128 + ri;
            float e = g_S[idx];
            sum += __logf(1.0f + neg / e);     // log(e+neg) - log(e)
        }
    }
    #pragma unroll
    for (int o = 16; o > 0; o >>= 1) sum += __shfl_xor_sync(0xffffffffu, sum, o);
    if (lane == 0) { g_rowloss[row] = sum / (float)cnt; g_rowP[row] = cnt; }
}

// ============ kernel 4: final fixed-order reduction ============
__global__ void k4_final(float* __restrict__ out) {
    __shared__ float sl[256];
    __shared__ int sp[256];
    int tid = threadIdx.x;
    float s = 0.0f; int p = 0;
    for (int i = tid; i < CN; i += 256) { s += g_rowloss[i]; p += g_rowP[i]; }
    sl[tid] = s; sp[tid] = p;
    __syncthreads();
    for (int st = 128; st > 0; st >>= 1) {
        if (tid < st) { sl[tid] += sl[tid + st]; sp[tid] += sp[tid + st]; }
        __syncthreads();
    }
    if (tid == 0) out[0] = sl[0] / (float)sp[0];
}

extern "C" void kernel_launch(void* const* d_in, const int* in_sizes, int n_in,
                              void* d_out, int out_size) {
    const float* F = (const float*)d_in[0];
    const int* T32 = (const int*)d_in[1];
    float* out = (float*)d_out;
    (void)in_sizes; (void)n_in; (void)out_size;

    cudaFuncSetAttribute(k2_gram_mma, cudaFuncAttributeMaxDynamicSharedMemorySize, SMEMSZ);

    k0_detect<<<1, 256>>>(T32);
    k1_normalize<<<CN, 128>>>(F, T32);
    k2b_lists<<<1, 1024>>>();
    k2_gram_mma<<<NPAIRS, 256, SMEMSZ>>>();
    k3_rowloss<<<CN / 8, 256>>>();
    k4_final<<<1, 256>>>(out);
}

// round 12
// speedup vs baseline: 1.5311x; 1.5311x over previous
#include <cuda_runtime.h>
#include <cstdint>

// ConLoss via mma.sync tf32 (R5 Gram kernel) + class member lists (R6 k3).
//   k0: target dtype detect   k1: row normalize
//   k2b: deterministic counting sort -> per-class member lists
//   k2: triangular 128x128 tf32 mma.sync tiles -> exp tile to g_S + neg partials
//   k3: per-row positive gather via member list
//   k4: final reduction
// Deterministic: no fp atomics; fixed-order reductions; stable sort.

#define CN 4096
#define CD 512
#define BM 128
#define NT (CN / BM)                  // 32
#define NPAIRS (NT * (NT + 1) / 2)    // 528
#define KC 64
#define NCHUNK (CD / KC)              // 8
#define KSTRIDE 68                    // padded smem row stride (floats)
#define NCLS 128                      // >= NUM_CLASSES(100), padded
#define EXP2SCALE 14.4269504088896340736f   // (1/TAU)*log2(e)

// ---- scratch ----
__device__ float g_Fn[CN * CD];                  // 8 MB normalized features
__device__ int   g_cls[CN];
__device__ float g_negpart[NT * CN];
__device__ float g_S[(size_t)NPAIRS * BM * BM];  // 34.6 MB exp(S/tau) tiles
__device__ float g_rowloss[CN];
__device__ int   g_rowP[CN];
__device__ int   g_is64;
__device__ int   g_mlist[CN];                    // members sorted by (class, j)
__device__ int   g_clsOff[NCLS];
__device__ int   g_clsCnt[NCLS];

// ============ kernel 0: detect targets dtype (int32 vs int64) ============
__global__ void k0_detect(const int* __restrict__ t32) {
    __shared__ int bad;
    if (threadIdx.x == 0) bad = 0;
    __syncthreads();
    for (int idx = 1 + 2 * threadIdx.x; idx < CN; idx += 2 * blockDim.x)
        if (t32[idx] != 0) bad = 1;
    __syncthreads();
    if (threadIdx.x == 0) g_is64 = bad ? 0 : 1;
}

// ============ kernel 1: normalize rows, cast labels ============
__global__ void k1_normalize(const float* __restrict__ F,
                             const int* __restrict__ t32) {
    int row = blockIdx.x;
    int tid = threadIdx.x;  // 128
    const float4* fr = (const float4*)(F + (size_t)row * CD);
    float4 x = fr[tid];
    float ss = x.x * x.x + x.y * x.y + x.z * x.z + x.w * x.w;
    #pragma unroll
    for (int o = 16; o > 0; o >>= 1) ss += __shfl_xor_sync(0xffffffffu, ss, o);
    __shared__ float ws[4];
    __shared__ float s_inv;
    int wid = tid >> 5, lane = tid & 31;
    if (lane == 0) ws[wid] = ss;
    __syncthreads();
    if (tid == 0) {
        float t = ws[0] + ws[1] + ws[2] + ws[3];
        s_inv = (t > 0.0f) ? rsqrtf(t) : 0.0f;
        g_cls[row] = g_is64 ? t32[2 * row] : t32[row];
    }
    __syncthreads();
    float inv = s_inv;
    ((float4*)(g_Fn + (size_t)row * CD))[tid] =
        make_float4(x.x * inv, x.y * inv, x.z * inv, x.w * inv);
}

// ============ kernel 2b: deterministic class member lists ============
__global__ __launch_bounds__(1024) void k2b_lists() {
    __shared__ int sCls[CN];            // 16 KB
    __shared__ int cnt[8][NCLS];        // chunk x class counts
    __shared__ int chOff[8][NCLS];
    __shared__ int clsOff[NCLS];
    int tid = threadIdx.x;
    for (int t = tid; t < CN; t += 1024) sCls[t] = g_cls[t];
    for (int t = tid; t < 8 * NCLS; t += 1024) ((int*)cnt)[t] = 0;
    __syncthreads();
    int ch = tid >> 7, sub = tid & 127;
    #pragma unroll
    for (int i = 0; i < 4; i++) {
        int j = ch * 512 + sub + i * 128;
        atomicAdd(&cnt[ch][sCls[j]], 1);     // integer counts: deterministic
    }
    __syncthreads();
    if (tid == 0) {
        int off = 0;
        for (int c = 0; c < NCLS; c++) {
            int tot = 0;
            #pragma unroll
            for (int h = 0; h < 8; h++) tot += cnt[h][c];
            clsOff[c] = off;
            g_clsOff[c] = off;
            g_clsCnt[c] = tot;
            off += tot;
        }
    }
    __syncthreads();
    if (tid < NCLS) {
        int run = clsOff[tid];
        #pragma unroll
        for (int h = 0; h < 8; h++) { chOff[h][tid] = run; run += cnt[h][tid]; }
    }
    __syncthreads();
    // stable placement: one thread per (chunk, class), scan chunk in j order
    if (tid < 8 * NCLS) {
        int c = tid & (NCLS - 1), h = tid >> 7;
        int pos = chOff[h][c];
        for (int j = h * 512; j < h * 512 + 512; j++)
            if (sCls[j] == c) g_mlist[pos++] = j;
    }
}

// ============ kernel 2: triangular Gram via mma.sync tf32 (R5 verbatim) ============
// smem: As[128][68] | Bs[128][68] | clsI[128] clsJ[128] | sMatR[2][128] | sMatC[4][128]
#define SM_FLOATS (2 * 128 * KSTRIDE + 256 + 256 + 512)
#define SMEMSZ (SM_FLOATS * 4)

__global__ __launch_bounds__(256, 2) void k2_gram_mma() {
    extern __shared__ float smem[];
    float* As = smem;
    float* Bs = smem + 128 * KSTRIDE;
    int* clsI = (int*)(smem + 2 * 128 * KSTRIDE);
    int* clsJ = clsI + 128;
    float* sMatR = (float*)(clsJ + 128);   // [2][128]
    float* sMatC = sMatR + 256;            // [4][128]

    int tid = threadIdx.x, wid = tid >> 5, lane = tid & 31;
    int b = blockIdx.x;
    int jT = (int)((sqrtf(8.0f * b + 1.0f) - 1.0f) * 0.5f);
    while ((jT + 1) * (jT + 2) / 2 <= b) jT++;
    while (jT * (jT + 1) / 2 > b) jT--;
    int iT = b - jT * (jT + 1) / 2;
    int i0 = iT * BM, j0 = jT * BM;
    bool diag = (iT == jT);

    if (tid < 128) {
        clsI[tid] = g_cls[i0 + tid];
        clsJ[tid] = g_cls[j0 + tid];
    }

    int wm = wid & 3, wn = wid >> 2;        // 4 x 2 warp grid
    int mrow0 = wm * 32, ncol0 = wn * 64;   // warp tile 32x64

    float acc[2][8][4];
    #pragma unroll
    for (int mf = 0; mf < 2; mf++)
        #pragma unroll
        for (int nf = 0; nf < 8; nf++)
            #pragma unroll
            for (int q = 0; q < 4; q++) acc[mf][nf][q] = 0.0f;

    // loader mapping: 8 threads cover 128B of one row; 2 halves (A/B)
    int half = tid >> 7, t = tid & 127;
    int lgrp = t >> 3;                      // 16 row groups
    int lc4 = t & 7;                        // float4 idx 0..7 (+8 second pass)
    const float* gsrc = g_Fn + (size_t)(half ? j0 : i0) * CD;
    float* sdst = half ? Bs : As;

    for (int c = 0; c < NCHUNK; c++) {
        int k0 = c * KC;
        __syncthreads();
        #pragma unroll
        for (int it = 0; it < 8; it++) {
            int row = lgrp + it * 16;
            #pragma unroll
            for (int h = 0; h < 2; h++) {
                int c4 = lc4 + h * 8;
                float4 v = *(const float4*)(gsrc + (size_t)row * CD + k0 + c4 * 4);
                uint32_t rx, ry, rz, rw;
                asm("cvt.rna.tf32.f32 %0, %1;" : "=r"(rx) : "f"(v.x));
                asm("cvt.rna.tf32.f32 %0, %1;" : "=r"(ry) : "f"(v.y));
                asm("cvt.rna.tf32.f32 %0, %1;" : "=r"(rz) : "f"(v.z));
                asm("cvt.rna.tf32.f32 %0, %1;" : "=r"(rw) : "f"(v.w));
                uint32_t* d = (uint32_t*)(sdst + row * KSTRIDE + c4 * 4);
                d[0] = rx; d[1] = ry; d[2] = rz; d[3] = rw;
            }
        }
        __syncthreads();
        #pragma unroll
        for (int kk = 0; kk < KC; kk += 8) {
            uint32_t a[2][4];
            int ar = mrow0 + (lane >> 2);
            int ak = kk + (lane & 3);
            #pragma unroll
            for (int mf = 0; mf < 2; mf++) {
                int r = ar + mf * 16;
                a[mf][0] = *(const uint32_t*)(As + r * KSTRIDE + ak);
                a[mf][1] = *(const uint32_t*)(As + (r + 8) * KSTRIDE + ak);
                a[mf][2] = *(const uint32_t*)(As + r * KSTRIDE + ak + 4);
                a[mf][3] = *(const uint32_t*)(As + (r + 8) * KSTRIDE + ak + 4);
            }
            #pragma unroll
            for (int nf = 0; nf < 8; nf++) {
                int n = ncol0 + nf * 8 + (lane >> 2);
                uint32_t b0 = *(const uint32_t*)(Bs + n * KSTRIDE + kk + (lane & 3));
                uint32_t b1 = *(const uint32_t*)(Bs + n * KSTRIDE + kk + (lane & 3) + 4);
                #pragma unroll
                for (int mf = 0; mf < 2; mf++) {
                    asm volatile(
                        "mma.sync.aligned.m16n8k8.row.col.f32.tf32.tf32.f32 "
                        "{%0,%1,%2,%3}, {%4,%5,%6,%7}, {%8,%9}, {%0,%1,%2,%3};"
                        : "+f"(acc[mf][nf][0]), "+f"(acc[mf][nf][1]),
                          "+f"(acc[mf][nf][2]), "+f"(acc[mf][nf][3])
                        : "r"(a[mf][0]), "r"(a[mf][1]), "r"(a[mf][2]), "r"(a[mf][3]),
                          "r"(b0), "r"(b1));
                }
            }
        }
    }

    // ---- epilogue: exp, mask, deterministic row/col partials, g_S store ----
    size_t pairBase = (size_t)b * (BM * BM);
    float rowP[2][2] = {{0, 0}, {0, 0}};
    float colP[8][2];
    #pragma unroll
    for (int nf = 0; nf < 8; nf++) { colP[nf][0] = 0.0f; colP[nf][1] = 0.0f; }

    int rr = mrow0 + (lane >> 2);
    int cc0 = ncol0 + (lane & 3) * 2;
    #pragma unroll
    for (int mf = 0; mf < 2; mf++) {
        int r = rr + mf * 16;
        int ci0 = clsI[r], ci1 = clsI[r + 8];
        #pragma unroll
        for (int nf = 0; nf < 8; nf++) {
            int col = cc0 + nf * 8;
            int cj0 = clsJ[col], cj1 = clsJ[col + 1];
            float e00 = exp2f(acc[mf][nf][0] * EXP2SCALE);
            float e01 = exp2f(acc[mf][nf][1] * EXP2SCALE);
            float e10 = exp2f(acc[mf][nf][2] * EXP2SCALE);
            float e11 = exp2f(acc[mf][nf][3] * EXP2SCALE);
            *(float2*)(g_S + pairBase + (size_t)r * BM + col) = make_float2(e00, e01);
            *(float2*)(g_S + pairBase + (size_t)(r + 8) * BM + col) = make_float2(e10, e11);
            float m00 = (ci0 != cj0) ? e00 : 0.0f;
            float m01 = (ci0 != cj1) ? e01 : 0.0f;
            float m10 = (ci1 != cj0) ? e10 : 0.0f;
            float m11 = (ci1 != cj1) ? e11 : 0.0f;
            rowP[mf][0] += m00 + m01;
            rowP[mf][1] += m10 + m11;
            colP[nf][0] += m00 + m10;
            colP[nf][1] += m01 + m11;
        }
    }
    #pragma unroll
    for (int mf = 0; mf < 2; mf++)
        #pragma unroll
        for (int h = 0; h < 2; h++) {
            float v = rowP[mf][h];
            v += __shfl_xor_sync(0xffffffffu, v, 1);
            v += __shfl_xor_sync(0xffffffffu, v, 2);
            rowP[mf][h] = v;
        }
    if ((lane & 3) == 0) {
        #pragma unroll
        for (int mf = 0; mf < 2; mf++) {
            int r = rr + mf * 16;
            sMatR[wn * 128 + r] = rowP[mf][0];
            sMatR[wn * 128 + r + 8] = rowP[mf][1];
        }
    }
    #pragma unroll
    for (int nf = 0; nf < 8; nf++)
        #pragma unroll
        for (int h = 0; h < 2; h++) {
            float v = colP[nf][h];
            v += __shfl_xor_sync(0xffffffffu, v, 4);
            v += __shfl_xor_sync(0xffffffffu, v, 8);
            v += __shfl_xor_sync(0xffffffffu, v, 16);
            colP[nf][h] = v;
        }
    if (lane < 4) {
        #pragma unroll
        for (int nf = 0; nf < 8; nf++) {
            int col = ncol0 + nf * 8 + lane * 2;
            sMatC[wm * 128 + col] = colP[nf][0];
            sMatC[wm * 128 + col + 1] = colP[nf][1];
        }
    }
    __syncthreads();
    if (tid < 128) {
        g_negpart[(size_t)jT * CN + i0 + tid] = sMatR[tid] + sMatR[128 + tid];
        if (!diag)
            g_negpart[(size_t)iT * CN + j0 + tid] =
                sMatC[tid] + sMatC[128 + tid] + sMatC[256 + tid] + sMatC[384 + tid];
    }
}

// ============ kernel 3: per-row positive gather (member lists) ============
__global__ __launch_bounds__(256) void k3_rowloss() {
    int tid = threadIdx.x, wid = tid >> 5, lane = tid & 31;
    int row = blockIdx.x * 8 + wid;

    float v = g_negpart[(size_t)lane * CN + row];
    #pragma unroll
    for (int o = 16; o > 0; o >>= 1) v += __shfl_xor_sync(0xffffffffu, v, o);
    float neg = v;

    int ci = g_cls[row];
    int off = g_clsOff[ci], cnt = g_clsCnt[ci];
    int ti = row >> 7, ri = row & 127;
    float sum = 0.0f;
    for (int m = lane; m < cnt; m += 32) {
        int j = g_mlist[off + m];
        if (j != row) {
            int tj = j >> 7, rj = j & 127;
            size_t idx = (ti <= tj)
                ? ((size_t)(tj * (tj + 1) / 2 + ti)) * 16384 + (size_t)ri * 128 + rj
                : ((size_t)(ti * (ti + 1) / 2 + tj)) * 16384 + (size_t)rj * 128 + ri;
            float e = g_S[idx];
            sum += __logf(1.0f + neg / e);     // log(e+neg) - log(e)
        }
    }
    #pragma unroll
    for (int o = 16; o > 0; o >>= 1) sum += __shfl_xor_sync(0xffffffffu, sum, o);
    if (lane == 0) { g_rowloss[row] = sum / (float)cnt; g_rowP[row] = cnt; }
}

// ============ kernel 4: final fixed-order reduction ============
__global__ void k4_final(float* __restrict__ out) {
    __shared__ float sl[256];
    __shared__ int sp[256];
    int tid = threadIdx.x;
    float s = 0.0f; int p = 0;
    for (int i = tid; i < CN; i += 256) { s += g_rowloss[i]; p += g_rowP[i]; }
    sl[tid] = s; sp[tid] = p;
    __syncthreads();
    for (int st = 128; st > 0; st >>= 1) {
        if (tid < st) { sl[tid] += sl[tid + st]; sp[tid] += sp[tid + st]; }
        __syncthreads();
    }
    if (tid == 0) out[0] = sl[0] / (float)sp[0];
}

extern "C" void kernel_launch(void* const* d_in, const int* in_sizes, int n_in,
                              void* d_out, int out_size) {
    const float* F = (const float*)d_in[0];
    const int* T32 = (const int*)d_in[1];
    float* out = (float*)d_out;
    (void)in_sizes; (void)n_in; (void)out_size;

    cudaFuncSetAttribute(k2_gram_mma, cudaFuncAttributeMaxDynamicSharedMemorySize, SMEMSZ);

    k0_detect<<<1, 256>>>(T32);
    k1_normalize<<<CN, 128>>>(F, T32);
    k2b_lists<<<1, 1024>>>();
    k2_gram_mma<<<NPAIRS, 256, SMEMSZ>>>();
    k3_rowloss<<<CN / 8, 256>>>();
    k4_final<<<1, 256>>>(out);
}